// round 5
// baseline (speedup 1.0000x reference)
#include <cuda_runtime.h>

// Windowed 3x3x3 correlation:
//   out[o=(i*9+j*3+k)][z][y][x] = (1/sqrt(32)) * sum_c fixed[c,z,y,x] * moving[c, z+i-1, y+j-1, x+k-1]
// fixed, moving: [32][96][96][96] fp32 (zero padding outside volume)

#define N 96
#define C 32
#define VOL (96 * 96 * 96)

// Block tile: 32 (x) x 8 (y) x 4 (z); threads (16,8,4)=512, each thread does VEC=2 along x.
#define BTX 16
#define BTY 8
#define BTZ 4
#define TILE_X 32        // BTX * 2
#define SMX_U 34         // used smem width (TILE_X + 2)
#define SMX 35           // padded stride (odd -> conflict-free)
#define SMY 10           // BTY + 2
#define SMZ 6            // BTZ + 2
#define SM_FILL (SMZ * SMY * SMX_U)   // 2040 elements
#define NSLOT 4          // ceil(2040 / 512)

__global__ __launch_bounds__(512)
void wincorr_kernel(const float* __restrict__ fixedp,
                    const float* __restrict__ movingp,
                    float* __restrict__ out)
{
    __shared__ float sm[SMZ * SMY * SMX];

    const int tx = threadIdx.x;                  // 0..15
    const int ty = threadIdx.y;                  // 0..7
    const int tz = threadIdx.z;                  // 0..3
    const int tid = tx + BTX * (ty + BTY * tz);  // 0..511

    const int x0 = blockIdx.x * TILE_X;
    const int y0 = blockIdx.y * BTY;
    const int z0 = blockIdx.z * BTZ;

    const int x = x0 + tx * 2;
    const int y = y0 + ty;
    const int z = z0 + tz;

    // ---- Hoisted halo-fill metadata (channel-invariant) ----
    int  smoff[NSLOT];
    int  gmoff[NSLOT];     // offset within one channel of moving
    bool active[NSLOT];    // idx < SM_FILL
    bool inside[NSLOT];    // source voxel in-bounds
#pragma unroll
    for (int s = 0; s < NSLOT; s++) {
        int idx = tid + s * 512;
        bool a = idx < SM_FILL;
        int lz = idx / (SMY * SMX_U);
        int r  = idx - lz * (SMY * SMX_U);
        int ly = r / SMX_U;
        int lx = r - ly * SMX_U;
        int gz = z0 - 1 + lz;
        int gy = y0 - 1 + ly;
        int gx = x0 - 1 + lx;
        bool in = a &&
                  (unsigned)gz < (unsigned)N &&
                  (unsigned)gy < (unsigned)N &&
                  (unsigned)gx < (unsigned)N;
        smoff[s]  = (lz * SMY + ly) * SMX + lx;
        gmoff[s]  = in ? (gz * N + gy) * N + gx : 0;
        active[s] = a;
        inside[s] = in;
    }

    float acc0[27];
    float acc1[27];
#pragma unroll
    for (int o = 0; o < 27; o++) { acc0[o] = 0.f; acc1[o] = 0.f; }

    const int fbase = ((z * N) + y) * N + x;

    for (int c = 0; c < C; c++) {
        const float* mv = movingp + c * VOL;

        // Halo tile fill: 4 predicated loads + stores, no index math in loop.
#pragma unroll
        for (int s = 0; s < NSLOT; s++) {
            if (active[s]) {
                float v = inside[s] ? __ldg(mv + gmoff[s]) : 0.f;
                sm[smoff[s]] = v;
            }
        }
        __syncthreads();

        // fixed values for this thread's two voxels (coalesced float2)
        const float2 f = *reinterpret_cast<const float2*>(
            fixedp + c * VOL + fbase);

#pragma unroll
        for (int i = 0; i < 3; i++) {
#pragma unroll
            for (int j = 0; j < 3; j++) {
                const float* row = &sm[((tz + i) * SMY + (ty + j)) * SMX + tx * 2];
                const float m0 = row[0];
                const float m1 = row[1];
                const float m2 = row[2];
                const float m3 = row[3];
                const int ob = (i * 3 + j) * 3;
                acc0[ob + 0] += f.x * m0;  acc1[ob + 0] += f.y * m1;
                acc0[ob + 1] += f.x * m1;  acc1[ob + 1] += f.y * m2;
                acc0[ob + 2] += f.x * m2;  acc1[ob + 2] += f.y * m3;
            }
        }
        __syncthreads();
    }

    const float scale = 0.17677669529663687f;  // 32^{-1/2}
    const int sp = (z * N + y) * N + x;
#pragma unroll
    for (int o = 0; o < 27; o++) {
        float2 r;
        r.x = acc0[o] * scale;
        r.y = acc1[o] * scale;
        *reinterpret_cast<float2*>(out + o * VOL + sp) = r;
    }
}

extern "C" void kernel_launch(void* const* d_in, const int* in_sizes, int n_in,
                              void* d_out, int out_size)
{
    const float* fixedp  = (const float*)d_in[0];
    const float* movingp = (const float*)d_in[1];
    float* out = (float*)d_out;

    dim3 block(BTX, BTY, BTZ);                 // 512 threads
    dim3 grid(N / TILE_X, N / BTY, N / BTZ);   // 3 x 12 x 24 = 864 blocks
    wincorr_kernel<<<grid, block>>>(fixedp, movingp, out);
}

// round 6
// speedup vs baseline: 2.6499x; 2.6499x over previous
#include <cuda_runtime.h>
#include <cstdint>

// Windowed 3x3x3 correlation:
//   out[o=(i*9+j*3+k)][z][y][x] = (1/sqrt(32)) * sum_c fixed[c,z,y,x] * moving[c, z+i-1, y+j-1, x+k-1]
// fixed, moving: [32][96][96][96] fp32 (zero padding outside volume)

#define N 96
#define C 32
#define VOL (96 * 96 * 96)

// Block tile: 32 (x) x 8 (y) x 4 (z); threads (16,8,4)=512, VEC=2 along x.
#define BTX 16
#define BTY 8
#define BTZ 4
#define TILE_X 32        // BTX * 2
#define SMX_U 34         // used smem width (TILE_X + 2)
#define SMX 35           // padded stride (odd -> conflict-free)
#define SMY 10           // BTY + 2
#define SMZ 6            // BTZ + 2
#define BUFSZ (SMZ * SMY * SMX)       // 2100 floats per buffer
#define SM_FILL (SMZ * SMY * SMX_U)   // 2040 elements to fill
#define NSLOT 4          // ceil(2040 / 512)

__device__ __forceinline__ void cp_async4(uint32_t saddr, const float* gsrc, int srcsize) {
    asm volatile("cp.async.ca.shared.global [%0], [%1], 4, %2;\n"
                 :: "r"(saddr), "l"(gsrc), "r"(srcsize));
}
__device__ __forceinline__ void cp_commit() {
    asm volatile("cp.async.commit_group;\n" ::: "memory");
}
__device__ __forceinline__ void cp_wait0() {
    asm volatile("cp.async.wait_group 0;\n" ::: "memory");
}

__global__ __launch_bounds__(512)
void wincorr_kernel(const float* __restrict__ fixedp,
                    const float* __restrict__ movingp,
                    float* __restrict__ out)
{
    __shared__ float sm[2 * BUFSZ];

    const int tx = threadIdx.x;                  // 0..15
    const int ty = threadIdx.y;                  // 0..7
    const int tz = threadIdx.z;                  // 0..3
    const int tid = tx + BTX * (ty + BTY * tz);  // 0..511

    const int x0 = blockIdx.x * TILE_X;
    const int y0 = blockIdx.y * BTY;
    const int z0 = blockIdx.z * BTZ;

    const int x = x0 + tx * 2;
    const int y = y0 + ty;
    const int z = z0 + tz;

    // ---- Hoisted halo-fill metadata (channel-invariant) ----
    uint32_t smaddr[NSLOT];       // shared address of slot (buffer 0)
    const float* gptr[NSLOT];     // global source (channel 0)
    int      szsrc[NSLOT];        // 4 if in-bounds else 0 (zero-fill)
    bool     active[NSLOT];
#pragma unroll
    for (int s = 0; s < NSLOT; s++) {
        int idx = tid + s * 512;
        bool a = idx < SM_FILL;
        int cidx = a ? idx : 0;
        int lz = cidx / (SMY * SMX_U);
        int r  = cidx - lz * (SMY * SMX_U);
        int ly = r / SMX_U;
        int lx = r - ly * SMX_U;
        int gz = z0 - 1 + lz;
        int gy = y0 - 1 + ly;
        int gx = x0 - 1 + lx;
        bool in = (unsigned)gz < (unsigned)N && (unsigned)gy < (unsigned)N &&
                  (unsigned)gx < (unsigned)N;
        int smoff = (lz * SMY + ly) * SMX + lx;
        smaddr[s] = (uint32_t)__cvta_generic_to_shared(sm + smoff);
        gptr[s]   = movingp + (in ? (gz * N + gy) * N + gx : 0);
        szsrc[s]  = in ? 4 : 0;
        active[s] = a;
    }

    float acc0[27];
    float acc1[27];
#pragma unroll
    for (int o = 0; o < 27; o++) { acc0[o] = 0.f; acc1[o] = 0.f; }

    const int fbase = ((z * N) + y) * N + x;
    const float* fptr = fixedp + fbase;

    // ---- Prologue: prefetch channel 0 tile + fixed ----
#pragma unroll
    for (int s = 0; s < NSLOT; s++)
        if (active[s]) cp_async4(smaddr[s], gptr[s], szsrc[s]);
    cp_commit();
    float2 fv = *reinterpret_cast<const float2*>(fptr);

#pragma unroll 2
    for (int c = 0; c < C; c++) {
        const int cur = c & 1;
        cp_wait0();              // tile for channel c landed
        __syncthreads();         // all warps done reading buf[cur] (prev use) + tile visible

        // Prefetch channel c+1 into the other buffer (overlaps compute below).
        if (c + 1 < C) {
            const uint32_t bofs = (cur ^ 1) * (BUFSZ * 4u);
            const float* nxt = movingp + (c + 1) * VOL;
#pragma unroll
            for (int s = 0; s < NSLOT; s++)
                if (active[s])
                    cp_async4(smaddr[s] + bofs, nxt + (gptr[s] - movingp), szsrc[s]);
            cp_commit();
        }

        const float2 f = fv;
        if (c + 1 < C)
            fv = *reinterpret_cast<const float2*>(fptr + (c + 1) * VOL);

        const float* buf = sm + cur * BUFSZ;
#pragma unroll
        for (int i = 0; i < 3; i++) {
#pragma unroll
            for (int j = 0; j < 3; j++) {
                const float* row = &buf[((tz + i) * SMY + (ty + j)) * SMX + tx * 2];
                const float m0 = row[0];
                const float m1 = row[1];
                const float m2 = row[2];
                const float m3 = row[3];
                const int ob = (i * 3 + j) * 3;
                acc0[ob + 0] += f.x * m0;  acc1[ob + 0] += f.y * m1;
                acc0[ob + 1] += f.x * m1;  acc1[ob + 1] += f.y * m2;
                acc0[ob + 2] += f.x * m2;  acc1[ob + 2] += f.y * m3;
            }
        }
    }

    const float scale = 0.17677669529663687f;  // 32^{-1/2}
    const int sp = (z * N + y) * N + x;
#pragma unroll
    for (int o = 0; o < 27; o++) {
        float2 r;
        r.x = acc0[o] * scale;
        r.y = acc1[o] * scale;
        *reinterpret_cast<float2*>(out + o * VOL + sp) = r;
    }
}

extern "C" void kernel_launch(void* const* d_in, const int* in_sizes, int n_in,
                              void* d_out, int out_size)
{
    const float* fixedp  = (const float*)d_in[0];
    const float* movingp = (const float*)d_in[1];
    float* out = (float*)d_out;

    dim3 block(BTX, BTY, BTZ);                 // 512 threads
    dim3 grid(N / TILE_X, N / BTY, N / BTZ);   // 3 x 12 x 24 = 864 blocks
    wincorr_kernel<<<grid, block>>>(fixedp, movingp, out);
}

// round 9
// speedup vs baseline: 3.3704x; 1.2719x over previous
#include <cuda_runtime.h>
#include <cstdint>

// Windowed 3x3x3 correlation:
//   out[o=(i*9+j*3+k)][z][y][x] = (1/sqrt(32)) * sum_c fixed[c,z,y,x] * moving[c, z+i-1, y+j-1, x+k-1]
// fixed, moving: [32][96][96][96] fp32 (zero padding outside volume)

#define N 96
#define C 32
#define VOL (96 * 96 * 96)

// Block tile: 32 (x) x 8 (y) x 4 (z); threads (16,8,4)=512, VEC=2 along x.
#define BTX 16
#define BTY 8
#define BTZ 4
#define TILE_X 32        // BTX * 2
#define SMX_U 34         // used smem width (TILE_X + 2)
#define SMX 36           // padded stride: EVEN -> every (row*SMX + tx*2) offset is 8B-aligned
#define SMY 10           // BTY + 2
#define SMZ 6            // BTZ + 2
#define BUFSZ (SMZ * SMY * SMX)       // 2160 floats per stage
#define SM_FILL (SMZ * SMY * SMX_U)   // 2040 elements to fill
#define NSLOT 4          // ceil(2040 / 512)
#define STAGES 4

__device__ __forceinline__ void cp_async4(uint32_t saddr, const float* gsrc, int srcsize) {
    asm volatile("cp.async.ca.shared.global [%0], [%1], 4, %2;\n"
                 :: "r"(saddr), "l"(gsrc), "r"(srcsize));
}
__device__ __forceinline__ void cp_commit() {
    asm volatile("cp.async.commit_group;\n" ::: "memory");
}
__device__ __forceinline__ void cp_wait2() {
    asm volatile("cp.async.wait_group 2;\n" ::: "memory");
}

// Packed f32x2 helpers (B300 FFMA2 — only reachable via PTX fma.rn.f32x2)
__device__ __forceinline__ unsigned long long pack2(float lo, float hi) {
    unsigned long long r;
    asm("mov.b64 %0, {%1, %2};"
        : "=l"(r) : "r"(__float_as_uint(lo)), "r"(__float_as_uint(hi)));
    return r;
}
__device__ __forceinline__ void ffma2(unsigned long long& d,
                                      unsigned long long a,
                                      unsigned long long b) {
    asm("fma.rn.f32x2 %0, %1, %2, %0;" : "+l"(d) : "l"(a), "l"(b));
}

__global__ __launch_bounds__(512, 1)
void wincorr_kernel(const float* __restrict__ fixedp,
                    const float* __restrict__ movingp,
                    float* __restrict__ out)
{
    __shared__ float sm[STAGES * BUFSZ];

    const int tx = threadIdx.x;                  // 0..15
    const int ty = threadIdx.y;                  // 0..7
    const int tz = threadIdx.z;                  // 0..3
    const int tid = tx + BTX * (ty + BTY * tz);  // 0..511

    const int x0 = blockIdx.x * TILE_X;
    const int y0 = blockIdx.y * BTY;
    const int z0 = blockIdx.z * BTZ;

    const int x = x0 + tx * 2;
    const int y = y0 + ty;
    const int z = z0 + tz;

    // ---- Hoisted halo-fill metadata (channel-invariant) ----
    uint32_t smaddr[NSLOT];       // shared address of slot (stage 0)
    int      gmoff[NSLOT];        // offset within one channel
    int      szsrc[NSLOT];        // 4 if in-bounds else 0 (zero-fill)
    bool     active[NSLOT];
#pragma unroll
    for (int s = 0; s < NSLOT; s++) {
        int idx = tid + s * 512;
        bool a = idx < SM_FILL;
        int cidx = a ? idx : 0;
        int lz = cidx / (SMY * SMX_U);
        int r  = cidx - lz * (SMY * SMX_U);
        int ly = r / SMX_U;
        int lx = r - ly * SMX_U;
        int gz = z0 - 1 + lz;
        int gy = y0 - 1 + ly;
        int gx = x0 - 1 + lx;
        bool in = (unsigned)gz < (unsigned)N && (unsigned)gy < (unsigned)N &&
                  (unsigned)gx < (unsigned)N;
        int smoff = (lz * SMY + ly) * SMX + lx;
        smaddr[s] = (uint32_t)__cvta_generic_to_shared(sm + smoff);
        gmoff[s]  = in ? (gz * N + gy) * N + gx : 0;
        szsrc[s]  = in ? 4 : 0;
        active[s] = a;
    }

    unsigned long long acc[27];
#pragma unroll
    for (int o = 0; o < 27; o++) acc[o] = 0ULL;

    const int fbase = ((z * N) + y) * N + x;
    const float* fptr = fixedp + fbase;

    // ---- Prologue: prefetch channels 0..2 into stages 0..2, fixed 0..1 ----
#pragma unroll
    for (int p = 0; p < STAGES - 1; p++) {
        const float* mv = movingp + p * VOL;
        const uint32_t bofs = p * (BUFSZ * 4u);
#pragma unroll
        for (int s = 0; s < NSLOT; s++)
            if (active[s]) cp_async4(smaddr[s] + bofs, mv + gmoff[s], szsrc[s]);
        cp_commit();
    }
    float2 fv0 = *reinterpret_cast<const float2*>(fptr);
    float2 fv1 = *reinterpret_cast<const float2*>(fptr + VOL);

    for (int c = 0; c < C; c++) {
        cp_wait2();              // stage for channel c landed (<=2 newer groups pending)
        __syncthreads();         // all warps done reading stage (c-1)&3 (overwritten next)

        // Prefetch channel c+3 into stage (c+3)&3 (the stage last read at c-1).
        if (c + 3 < C) {
            const uint32_t bofs = ((c + 3) & (STAGES - 1)) * (BUFSZ * 4u);
            const float* nxt = movingp + (c + 3) * VOL;
#pragma unroll
            for (int s = 0; s < NSLOT; s++)
                if (active[s]) cp_async4(smaddr[s] + bofs, nxt + gmoff[s], szsrc[s]);
        }
        cp_commit();             // always commit (empty groups keep wait count uniform)

        const float2 f = fv0;
        fv0 = fv1;
        if (c + 2 < C)
            fv1 = *reinterpret_cast<const float2*>(fptr + (c + 2) * VOL);

        const unsigned long long fp = pack2(f.x, f.y);
        const float* buf = sm + (c & (STAGES - 1)) * BUFSZ;

#pragma unroll
        for (int i = 0; i < 3; i++) {
#pragma unroll
            for (int j = 0; j < 3; j++) {
                // 8B-aligned LDS.64 pair (SMX even, tx*2 even) — conflict-free.
                const float* row = &buf[((tz + i) * SMY + (ty + j)) * SMX + tx * 2];
                const float2 m01 = *reinterpret_cast<const float2*>(row);
                const float2 m23 = *reinterpret_cast<const float2*>(row + 2);
                const int ob = (i * 3 + j) * 3;
                ffma2(acc[ob + 0], fp, pack2(m01.x, m01.y));
                ffma2(acc[ob + 1], fp, pack2(m01.y, m23.x));
                ffma2(acc[ob + 2], fp, pack2(m23.x, m23.y));
            }
        }
    }

    const float scale = 0.17677669529663687f;  // 32^{-1/2}
    const int sp = (z * N + y) * N + x;
#pragma unroll
    for (int o = 0; o < 27; o++) {
        unsigned int lo, hi;
        asm("mov.b64 {%0, %1}, %2;" : "=r"(lo), "=r"(hi) : "l"(acc[o]));
        float2 r;
        r.x = __uint_as_float(lo) * scale;
        r.y = __uint_as_float(hi) * scale;
        *reinterpret_cast<float2*>(out + o * VOL + sp) = r;
    }
}

extern "C" void kernel_launch(void* const* d_in, const int* in_sizes, int n_in,
                              void* d_out, int out_size)
{
    const float* fixedp  = (const float*)d_in[0];
    const float* movingp = (const float*)d_in[1];
    float* out = (float*)d_out;

    dim3 block(BTX, BTY, BTZ);                 // 512 threads
    dim3 grid(N / TILE_X, N / BTY, N / BTZ);   // 3 x 12 x 24 = 864 blocks
    wincorr_kernel<<<grid, block>>>(fixedp, movingp, out);
}

// round 10
// speedup vs baseline: 3.8717x; 1.1487x over previous
#include <cuda_runtime.h>
#include <cstdint>

// Windowed 3x3x3 correlation:
//   out[o=(i*9+j*3+k)][z][y][x] = (1/sqrt(32)) * sum_c fixed[c,z,y,x] * moving[c, z+i-1, y+j-1, x+k-1]
// fixed, moving: [32][96][96][96] fp32 (zero padding outside volume)

#define N 96
#define C 32
#define VOL (96 * 96 * 96)

// Block tile: 32 (x) x 8 (y) x 2 (z); threads (16,8,2)=256, VEC=2 along x.
// 256 threads x ~120 regs -> 2 CTAs/SM (independent barriers cover each other's bubbles).
#define BTX 16
#define BTY 8
#define BTZ 2
#define NTHR 256
#define TILE_X 32        // BTX * 2
#define SMX_U 34         // used smem width (TILE_X + 2)
#define SMX 36           // padded stride: EVEN -> (row*SMX + tx*2) is 8B-aligned
#define SMY 10           // BTY + 2
#define SMZ 4            // BTZ + 2
#define BUFSZ (SMZ * SMY * SMX)       // 1440 floats per stage
#define SM_FILL (SMZ * SMY * SMX_U)   // 1360 elements to fill
#define NSLOT 6          // ceil(1360 / 256)
#define STAGES 4

__device__ __forceinline__ void cp_async4(uint32_t saddr, const float* gsrc, int srcsize) {
    asm volatile("cp.async.ca.shared.global [%0], [%1], 4, %2;\n"
                 :: "r"(saddr), "l"(gsrc), "r"(srcsize));
}
__device__ __forceinline__ void cp_commit() {
    asm volatile("cp.async.commit_group;\n" ::: "memory");
}
__device__ __forceinline__ void cp_wait2() {
    asm volatile("cp.async.wait_group 2;\n" ::: "memory");
}

// Packed f32x2 helpers (B300 FFMA2 — only reachable via PTX fma.rn.f32x2)
__device__ __forceinline__ unsigned long long pack2(float lo, float hi) {
    unsigned long long r;
    asm("mov.b64 %0, {%1, %2};"
        : "=l"(r) : "r"(__float_as_uint(lo)), "r"(__float_as_uint(hi)));
    return r;
}
__device__ __forceinline__ void ffma2(unsigned long long& d,
                                      unsigned long long a,
                                      unsigned long long b) {
    asm("fma.rn.f32x2 %0, %1, %2, %0;" : "+l"(d) : "l"(a), "l"(b));
}

__global__ __launch_bounds__(NTHR, 2)
void wincorr_kernel(const float* __restrict__ fixedp,
                    const float* __restrict__ movingp,
                    float* __restrict__ out)
{
    __shared__ float sm[STAGES * BUFSZ];

    const int tx = threadIdx.x;                  // 0..15
    const int ty = threadIdx.y;                  // 0..7
    const int tz = threadIdx.z;                  // 0..1
    const int tid = tx + BTX * (ty + BTY * tz);  // 0..255

    const int x0 = blockIdx.x * TILE_X;
    const int y0 = blockIdx.y * BTY;
    const int z0 = blockIdx.z * BTZ;

    const int x = x0 + tx * 2;
    const int y = y0 + ty;
    const int z = z0 + tz;

    // ---- Hoisted halo-fill metadata (channel-invariant) ----
    uint32_t smaddr[NSLOT];       // shared address of slot (stage 0)
    int      gmoff[NSLOT];        // offset within one channel
    int      szsrc[NSLOT];        // 4 if in-bounds else 0 (zero-fill)
    bool     active[NSLOT];
#pragma unroll
    for (int s = 0; s < NSLOT; s++) {
        int idx = tid + s * NTHR;
        bool a = idx < SM_FILL;
        int cidx = a ? idx : 0;
        int lz = cidx / (SMY * SMX_U);
        int r  = cidx - lz * (SMY * SMX_U);
        int ly = r / SMX_U;
        int lx = r - ly * SMX_U;
        int gz = z0 - 1 + lz;
        int gy = y0 - 1 + ly;
        int gx = x0 - 1 + lx;
        bool in = (unsigned)gz < (unsigned)N && (unsigned)gy < (unsigned)N &&
                  (unsigned)gx < (unsigned)N;
        int smoff = (lz * SMY + ly) * SMX + lx;
        smaddr[s] = (uint32_t)__cvta_generic_to_shared(sm + smoff);
        gmoff[s]  = in ? (gz * N + gy) * N + gx : 0;
        szsrc[s]  = in ? 4 : 0;
        active[s] = a;
    }

    unsigned long long acc[27];
#pragma unroll
    for (int o = 0; o < 27; o++) acc[o] = 0ULL;

    const int fbase = ((z * N) + y) * N + x;
    const float* fptr = fixedp + fbase;

    // ---- Prologue: prefetch channels 0..2 into stages 0..2, fixed 0..1 ----
#pragma unroll
    for (int p = 0; p < STAGES - 1; p++) {
        const float* mv = movingp + p * VOL;
        const uint32_t bofs = p * (BUFSZ * 4u);
#pragma unroll
        for (int s = 0; s < NSLOT; s++)
            if (active[s]) cp_async4(smaddr[s] + bofs, mv + gmoff[s], szsrc[s]);
        cp_commit();
    }
    float2 fv0 = *reinterpret_cast<const float2*>(fptr);
    float2 fv1 = *reinterpret_cast<const float2*>(fptr + VOL);

    for (int c = 0; c < C; c++) {
        cp_wait2();              // stage for channel c landed (<=2 newer groups pending)
        __syncthreads();         // all warps done reading stage (c-1)&3 (overwritten next)

        // Prefetch channel c+3 into stage (c+3)&3 (the stage last read at c-1).
        if (c + 3 < C) {
            const uint32_t bofs = ((c + 3) & (STAGES - 1)) * (BUFSZ * 4u);
            const float* nxt = movingp + (c + 3) * VOL;
#pragma unroll
            for (int s = 0; s < NSLOT; s++)
                if (active[s]) cp_async4(smaddr[s] + bofs, nxt + gmoff[s], szsrc[s]);
        }
        cp_commit();             // always commit (empty groups keep wait count uniform)

        const float2 f = fv0;
        fv0 = fv1;
        if (c + 2 < C)
            fv1 = *reinterpret_cast<const float2*>(fptr + (c + 2) * VOL);

        const unsigned long long fp = pack2(f.x, f.y);
        const float* buf = sm + (c & (STAGES - 1)) * BUFSZ;

#pragma unroll
        for (int i = 0; i < 3; i++) {
#pragma unroll
            for (int j = 0; j < 3; j++) {
                // 8B-aligned LDS.64 pair (SMX even, tx*2 even) — conflict-free.
                const float* row = &buf[((tz + i) * SMY + (ty + j)) * SMX + tx * 2];
                const unsigned long long m01 =
                    *reinterpret_cast<const unsigned long long*>(row);       // (m0,m1)
                const unsigned long long m23 =
                    *reinterpret_cast<const unsigned long long*>(row + 2);   // (m2,m3)
                // cross pair (m1,m2) — the only pack needed
                unsigned int r0, r1, r2, r3;
                asm("mov.b64 {%0, %1}, %2;" : "=r"(r0), "=r"(r1) : "l"(m01));
                asm("mov.b64 {%0, %1}, %2;" : "=r"(r2), "=r"(r3) : "l"(m23));
                unsigned long long m12;
                asm("mov.b64 %0, {%1, %2};" : "=l"(m12) : "r"(r1), "r"(r2));
                const int ob = (i * 3 + j) * 3;
                ffma2(acc[ob + 0], fp, m01);
                ffma2(acc[ob + 1], fp, m12);
                ffma2(acc[ob + 2], fp, m23);
            }
        }
    }

    const float scale = 0.17677669529663687f;  // 32^{-1/2}
    const int sp = (z * N + y) * N + x;
#pragma unroll
    for (int o = 0; o < 27; o++) {
        unsigned int lo, hi;
        asm("mov.b64 {%0, %1}, %2;" : "=r"(lo), "=r"(hi) : "l"(acc[o]));
        float2 r;
        r.x = __uint_as_float(lo) * scale;
        r.y = __uint_as_float(hi) * scale;
        *reinterpret_cast<float2*>(out + o * VOL + sp) = r;
    }
}

extern "C" void kernel_launch(void* const* d_in, const int* in_sizes, int n_in,
                              void* d_out, int out_size)
{
    const float* fixedp  = (const float*)d_in[0];
    const float* movingp = (const float*)d_in[1];
    float* out = (float*)d_out;

    dim3 block(BTX, BTY, BTZ);                 // 256 threads
    dim3 grid(N / TILE_X, N / BTY, N / BTZ);   // 3 x 12 x 48 = 1728 blocks
    wincorr_kernel<<<grid, block>>>(fixedp, movingp, out);
}